// round 13
// baseline (speedup 1.0000x reference)
#include <cuda_runtime.h>
#include <cuda_fp16.h>
#include <cstdint>

// ---------------------------------------------------------------------------
// AdaptiveSoftmax — fp16 mma.sync, K=64 tiles, 2-slot cp.async ring with
// immediate-offset smem addressing, fused-CE epilogue, merged launches.
//   0: w_in [4096,1024] f32   1: target [4096] i32
//   2: head_w [2002,1024] f32 3: head_b [2002] f32
//   4: tail0_w1 [1024,1024]   5: tail0_w2 [8000,1024]
//   6: tail1_w1 [256,1024]    7: tail1_w2 [40000,256]
//   out: scalar f32 loss
// ---------------------------------------------------------------------------

#define N_TOK 4096
#define PT_STRIDE 632   // >= 625 N-tiles (tail1, 64-wide)

// fp16 operands in kt32-tiled layout: u32 idx = ((kt*R + row)*16 + slot)
// slot(p) = (p&3)*4 + (p>>2) for kpair p in k-tile of 32 halves.
__device__ __align__(16) uint32_t d_winh [2097152];
__device__ __align__(16) uint32_t d_hwh  [1025024];
__device__ __align__(16) uint32_t d_t0w1h[524288];
__device__ __align__(16) uint32_t d_t0w2h[4096000];
__device__ __align__(16) uint32_t d_t1w1h[131072];
__device__ __align__(16) uint32_t d_t1w2h[5120000];
__device__ __align__(16) uint32_t d_h0h  [2097152];   // R=4096, K=1024
__device__ __align__(16) uint32_t d_h1h  [524288];    // R=4096, K=256

__device__ __align__(16) float2 d_part[(size_t)3 * N_TOK * PT_STRIDE];
__device__ float d_labv[3 * N_TOK];
__device__ float d_nllv[3 * N_TOK];
__device__ int   d_labh[N_TOK];
__device__ int   d_lab0[N_TOK];
__device__ int   d_lab1[N_TOK];
__device__ int   d_idx0[N_TOK];
__device__ int   d_idx1[N_TOK];
__device__ int   d_cnt0;
__device__ int   d_cnt1;

// ---------------------------------------------------------------------------
__global__ void init_kernel() {
    if (threadIdx.x == 0) { d_cnt0 = 0; d_cnt1 = 0; }
}

__global__ void gather_kernel(const int* __restrict__ target) {
    int i = blockIdx.x * blockDim.x + threadIdx.x;
    if (i >= N_TOK) return;
    int t = target[i];
    int labh = t;
    if (t >= 2000 && t < 10000) {
        labh = 2000;
        int p = atomicAdd(&d_cnt0, 1);
        if (p < N_TOK) { d_idx0[p] = i; d_lab0[p] = t - 2000; }
    } else if (t >= 10000 && t < 50000) {
        labh = 2001;
        int p = atomicAdd(&d_cnt1, 1);
        if (p < N_TOK) { d_idx1[p] = i; d_lab1[p] = t - 10000; }
    }
    d_labh[i] = min(max(labh, 0), 2001);
}

// ---------------------------------------------------------------------------
__device__ __forceinline__ uint32_t pack_h2(float x, float y) {
    __half2 h = __floats2half2_rn(x, y);
    return *reinterpret_cast<uint32_t*>(&h);
}

#define W0 524288
#define W1 256256
#define W2 131072
#define W3 1024000
#define W4 32768
#define W5 1280000
#define WTOT (W0+W1+W2+W3+W4+W5)

__global__ __launch_bounds__(256)
void convert_kernel(const float* __restrict__ w_in, const float* __restrict__ head_w,
                    const float* __restrict__ t0w1, const float* __restrict__ t0w2,
                    const float* __restrict__ t1w1, const float* __restrict__ t1w2) {
    int i = blockIdx.x * 256 + threadIdx.x;
    if (i >= WTOT) return;
    const float* src; uint32_t* dst; int R, K, c = i;
    if (c < W0)              { src = w_in;   dst = d_winh;  R = 4096;  K = 1024; }
    else if ((c -= W0) < W1) { src = head_w; dst = d_hwh;   R = 2002;  K = 1024; }
    else if ((c -= W1) < W2) { src = t0w1;   dst = d_t0w1h; R = 1024;  K = 1024; }
    else if ((c -= W2) < W3) { src = t0w2;   dst = d_t0w2h; R = 8000;  K = 1024; }
    else if ((c -= W3) < W4) { src = t1w1;   dst = d_t1w1h; R = 256;   K = 1024; }
    else      { c -= W4;       src = t1w2;   dst = d_t1w2h; R = 40000; K = 256;  }
    int nrow4 = R * 4;
    int kt = c / nrow4;
    int rem = c - kt * nrow4;
    int r = rem >> 2, g = rem & 3;
    const float* s = src + (size_t)r * K + kt * 32 + 2 * g;
    uint4 o;
    o.x = pack_h2(s[0],  s[1]);
    o.y = pack_h2(s[8],  s[9]);
    o.z = pack_h2(s[16], s[17]);
    o.w = pack_h2(s[24], s[25]);
    reinterpret_cast<uint4*>(dst)[((size_t)kt * R + r) * 4 + g] = o;
}

// ---------------------------------------------------------------------------
__device__ __forceinline__ void mma_f16(float* d, uint32_t a0, uint32_t a1,
                                        uint32_t a2, uint32_t a3,
                                        uint32_t b0, uint32_t b1) {
    asm volatile(
        "mma.sync.aligned.m16n8k16.row.col.f32.f16.f16.f32 "
        "{%0,%1,%2,%3}, {%4,%5,%6,%7}, {%8,%9}, {%0,%1,%2,%3};"
        : "+f"(d[0]), "+f"(d[1]), "+f"(d[2]), "+f"(d[3])
        : "r"(a0), "r"(a1), "r"(a2), "r"(a3), "r"(b0), "r"(b1));
}

template<int IMM>
__device__ __forceinline__ uint4 lds128i(uint32_t a) {
    uint4 v;
    asm volatile("ld.shared.v4.b32 {%0,%1,%2,%3}, [%4+%5];"
                 : "=r"(v.x), "=r"(v.y), "=r"(v.z), "=r"(v.w)
                 : "r"(a), "n"(IMM));
    return v;
}
template<int DOFF, int SOFF>
__device__ __forceinline__ void cp16i(uint32_t d, const uint32_t* g) {
    asm volatile("cp.async.cg.shared.global [%0+%2], [%1+%3], 16;"
                 :: "r"(d), "l"(g), "n"(DOFF), "n"(SOFF));
}
__device__ __forceinline__ void cp_commit() {
    asm volatile("cp.async.commit_group;" ::: "memory");
}
template<int G>
__device__ __forceinline__ void cp_waitg() {
    asm volatile("cp.async.wait_group %0;" :: "n"(G) : "memory");
}

__device__ __forceinline__ void ol_merge(float& mx, float& sm, float om, float os) {
    float nm = fmaxf(mx, om);
    sm = sm * __expf(mx - nm) + os * __expf(om - nm);
    mx = nm;
}

// ---------------------------------------------------------------------------
// Unified GEMM: block 128x64 x K64, 256 thr, 8 warps (4m x 2n), warp 32x32.
// Smem (u32): A slot s at [s*4096] (2 sub-tiles of 2048), B slot s at
// [8192 + s*2048] (2 sub-tiles of 1024). 48KB total, 2-slot ring.
// CE spart aliases slot 0 (safe: nk64 even -> last tile in slot 1).
// ---------------------------------------------------------------------------
#define LOAD_TILE(S) do {                                                   \
    cp16i<(S)*16384,          0>(dA0, agp);                                 \
    cp16i<(S)*16384,         16>(dA1, agp);                                 \
    cp16i<(S)*16384 + 8192, 262144>(dA0, agp);                              \
    cp16i<(S)*16384 + 8192, 262160>(dA1, agp);                              \
    cp16i<32768 + (S)*8192,        0>(dBd, bgp0);                           \
    cp16i<32768 + (S)*8192 + 4096, 0>(dBd, bgp1);                           \
    cp_commit();                                                            \
    agp  += 131072;                                                         \
    bgp0 += bStep; bgp1 += bStep;                                           \
} while (0)

#define COMPUTE_SUB(AIMM, BIMM) do {                                        \
    uint4 bf[4];                                                            \
    _Pragma("unroll")                                                       \
    for (int nt = 0; nt < 4; nt++) bf[nt] = lds128i<(BIMM)>(bF[nt]);        \
    _Pragma("unroll")                                                       \
    for (int mt = 0; mt < 2; mt++) {                                        \
        uint4 lo = lds128i<(AIMM)>(aF[mt][0]);                              \
        uint4 hi = lds128i<(AIMM)>(aF[mt][1]);                              \
        _Pragma("unroll")                                                   \
        for (int nt = 0; nt < 4; nt++)                                      \
            mma_f16(acc[mt][nt], lo.x, hi.x, lo.y, hi.y, bf[nt].x, bf[nt].y);\
        _Pragma("unroll")                                                   \
        for (int nt = 0; nt < 4; nt++)                                      \
            mma_f16(acc[mt][nt], lo.z, hi.z, lo.w, hi.w, bf[nt].z, bf[nt].w);\
    }                                                                       \
} while (0)

#define COMPUTE_TILE(S) do {                                                \
    COMPUTE_SUB((S)*16384,        32768 + (S)*8192);                        \
    COMPUTE_SUB((S)*16384 + 8192, 32768 + (S)*8192 + 4096);                 \
} while (0)

__global__ __launch_bounds__(256, 3)
void gemm256(const float* __restrict__ bias, int stage) {
    int z = blockIdx.z;
    const uint32_t *A, *Bw;
    uint32_t* Cout = nullptr;
    const int* idxArr = nullptr;
    const int* labArr = nullptr;
    int N, K, cnt, xmax, ce = 0, phase = 0;
    bool useBias = false;
    if (stage == 0) {
        if (z == 0)      { A = d_winh; Bw = d_hwh;   N = 2002; K = 1024; cnt = N_TOK;
                           xmax = 32; ce = 1; phase = 0; labArr = d_labh; useBias = true; }
        else if (z == 1) { A = d_winh; Bw = d_t0w1h; N = 1024; K = 1024; cnt = d_cnt0;
                           xmax = 16; idxArr = d_idx0; Cout = d_h0h; }
        else             { A = d_winh; Bw = d_t1w1h; N = 256;  K = 1024; cnt = d_cnt1;
                           xmax = 4; idxArr = d_idx1; Cout = d_h1h; }
    } else {
        if (z == 0)      { A = d_h1h; Bw = d_t1w2h; N = 40000; K = 256;  cnt = d_cnt1;
                           xmax = 625; ce = 1; phase = 2; labArr = d_lab1; }
        else             { A = d_h0h; Bw = d_t0w2h; N = 8000;  K = 1024; cnt = d_cnt0;
                           xmax = 125; ce = 1; phase = 1; labArr = d_lab0; }
    }
    if ((int)blockIdx.x >= xmax) return;
    if (cnt > N_TOK) cnt = N_TOK;
    int m0 = blockIdx.y * 128;
    int n0 = blockIdx.x * 64;
    if (m0 >= cnt) return;

    __shared__ __align__(16) uint32_t Smem[12288];   // 48KB
    float2 (*spart)[2] = reinterpret_cast<float2(*)[2]>(Smem);  // aliases slot 0

    int tid  = threadIdx.x;
    int lane = tid & 31;
    int warp = tid >> 5;
    int wm = warp & 3;       // m offset wm*32
    int wn = warp >> 2;      // n offset wn*32

    uint32_t smemBase = (uint32_t)__cvta_generic_to_shared(Smem);

    // ---- loader dst addresses (per kt32 sub-tile pattern) ----
    int lrow = tid >> 1;
    int hh   = tid & 1;
    int g0 = 2 * hh, g1 = 2 * hh + 1;
    int swzA = (lrow >> 1) & 3;
    uint32_t dA0 = smemBase + ((lrow * 16 + 4 * (g0 ^ swzA)) << 2);
    uint32_t dA1 = smemBase + ((lrow * 16 + 4 * (g1 ^ swzA)) << 2);
    int brW = tid >> 2;
    int gB  = tid & 3;
    uint32_t dBd = smemBase + ((brW * 16 + 4 * (gB ^ ((brW >> 1) & 3))) << 2);

    int am = m0 + lrow;
    int arow = (am < cnt) ? (idxArr ? idxArr[am] : am) : 0;
    arow = min(max(arow, 0), N_TOK - 1);
    int brow = min(n0 + brW, N - 1);

    const uint32_t* agp  = A  + (size_t)arow * 16 + 4 * g0;
    const uint32_t* bgp0 = Bw + (size_t)brow * 16 + 4 * gB;
    const uint32_t* bgp1 = bgp0 + (size_t)N * 16;
    const size_t bStep = (size_t)N * 32;

    // ---- fragment base addresses (loop-invariant) ----
    int gq = lane >> 2;
    int tq = lane & 3;
    uint32_t aF[2][2], bF[4];
#pragma unroll
    for (int mt = 0; mt < 2; mt++) {
        int ra = wm * 32 + mt * 16 + gq;
        int ga = tq ^ ((ra >> 1) & 3);
        aF[mt][0] = smemBase + ((ra * 16 + 4 * ga) << 2);
        int rh = ra + 8;
        int gh = tq ^ ((rh >> 1) & 3);
        aF[mt][1] = smemBase + ((rh * 16 + 4 * gh) << 2);
    }
#pragma unroll
    for (int nt = 0; nt < 4; nt++) {
        int rb = wn * 32 + nt * 8 + gq;
        int gb = tq ^ ((rb >> 1) & 3);
        bF[nt] = smemBase + ((rb * 16 + 4 * gb) << 2);
    }

    float acc[2][4][4];
#pragma unroll
    for (int mt = 0; mt < 2; mt++)
#pragma unroll
        for (int nt = 0; nt < 4; nt++)
#pragma unroll
            for (int e = 0; e < 4; e++) acc[mt][nt][e] = 0.0f;

    int nk64 = K >> 6;    // 16 or 4 (even)
    LOAD_TILE(0);         // tile 0 -> slot 0
    for (int kt0 = 0; kt0 < nk64; kt0 += 2) {
        if (kt0 + 1 < nk64) { LOAD_TILE(1); cp_waitg<1>(); }
        else                  cp_waitg<0>();
        __syncthreads();
        COMPUTE_TILE(0);
        __syncthreads();
        if (kt0 + 2 < nk64) { LOAD_TILE(0); cp_waitg<1>(); }
        else                  cp_waitg<0>();
        __syncthreads();
        COMPUTE_TILE(1);
        __syncthreads();
    }

    if (ce) {
        // ---- fused CE epilogue ----
        float* labv = d_labv + phase * N_TOK;
#pragma unroll
        for (int mt = 0; mt < 2; mt++) {
#pragma unroll
            for (int h = 0; h < 2; h++) {
                int rloc = wm * 32 + mt * 16 + gq + h * 8;
                int m = m0 + rloc;
                bool ok = (m < cnt);
                int lab = ok ? labArr[m] : -1;
                float mx = -1e30f, sm = 0.f;
#pragma unroll
                for (int nt = 0; nt < 4; nt++) {
#pragma unroll
                    for (int e = 0; e < 2; e++) {
                        int col = n0 + wn * 32 + nt * 8 + tq * 2 + e;
                        if (col < N) {
                            float v = acc[mt][nt][h * 2 + e];
                            if (useBias) v += bias[col];
                            mx = fmaxf(mx, v);
                        }
                    }
                }
#pragma unroll
                for (int nt = 0; nt < 4; nt++) {
#pragma unroll
                    for (int e = 0; e < 2; e++) {
                        int col = n0 + wn * 32 + nt * 8 + tq * 2 + e;
                        if (col < N) {
                            float v = acc[mt][nt][h * 2 + e];
                            if (useBias) v += bias[col];
                            sm += __expf(v - mx);
                            if (ok && col == lab) labv[m] = v;
                        }
                    }
                }
#pragma unroll
                for (int off = 1; off <= 2; off <<= 1) {
                    float om = __shfl_xor_sync(0xffffffff, mx, off);
                    float os = __shfl_xor_sync(0xffffffff, sm, off);
                    ol_merge(mx, sm, om, os);
                }
                if (tq == 0) spart[rloc][wn] = make_float2(mx, sm);
            }
        }
        __syncthreads();
        if (tid < 128) {
            float mx = -1e30f, sm = 0.f;
#pragma unroll
            for (int w = 0; w < 2; w++) {
                float2 p = spart[tid][w];
                ol_merge(mx, sm, p.x, p.y);
            }
            int m = m0 + tid;
            if (m < cnt)
                d_part[((size_t)phase * N_TOK + m) * PT_STRIDE + blockIdx.x] =
                    make_float2(mx, sm);
        }
        return;
    }

    // ---- plain epilogue: write h in kt32-tiled fp16 layout ----
#pragma unroll
    for (int mt = 0; mt < 2; mt++) {
#pragma unroll
        for (int h = 0; h < 2; h++) {
            int r = m0 + wm * 32 + mt * 16 + gq + h * 8;
            if (r >= cnt) continue;
#pragma unroll
            for (int nt = 0; nt < 4; nt++) {
                int cb = n0 + wn * 32 + nt * 8 + tq * 2;
                int kt = cb >> 5;
                int p  = (cb & 31) >> 1;
                int s  = (p & 3) * 4 + (p >> 2);
                Cout[((size_t)kt * 4096 + r) * 16 + s] =
                    pack_h2(acc[mt][nt][h * 2 + 0], acc[mt][nt][h * 2 + 1]);
            }
        }
    }
}

// ---------------------------------------------------------------------------
__global__ __launch_bounds__(32)
void ce_merge() {
    int phase = blockIdx.y;
    int ntiles = (phase == 0) ? 32 : ((phase == 1) ? 125 : 625);
    int cnt    = (phase == 0) ? N_TOK : ((phase == 1) ? d_cnt0 : d_cnt1);
    if (cnt > N_TOK) cnt = N_TOK;
    int b = blockIdx.x;
    if (b >= cnt) return;
    int lane = threadIdx.x;

    const float2* base = d_part + ((size_t)phase * N_TOK + b) * PT_STRIDE;
    float mx = -1e30f, sm = 0.f;
    for (int t = lane; t < ntiles; t += 32) {
        float2 p = base[t];
        ol_merge(mx, sm, p.x, p.y);
    }
#pragma unroll
    for (int off = 16; off > 0; off >>= 1) {
        float om = __shfl_xor_sync(0xffffffff, mx, off);
        float os = __shfl_xor_sync(0xffffffff, sm, off);
        ol_merge(mx, sm, om, os);
    }
    if (lane == 0)
        d_nllv[phase * N_TOK + b] = logf(sm) + mx - d_labv[phase * N_TOK + b];
}

__global__ __launch_bounds__(1024)
void reduce_kernel(float* __restrict__ out) {
    __shared__ double s[1024];
    int c0 = min(d_cnt0, N_TOK), c1 = min(d_cnt1, N_TOK);
    double a = 0.0;
    for (int i = threadIdx.x; i < N_TOK; i += 1024) a += (double)d_nllv[i];
    for (int i = threadIdx.x; i < c0;    i += 1024) a += (double)d_nllv[N_TOK + i];
    for (int i = threadIdx.x; i < c1;    i += 1024) a += (double)d_nllv[2 * N_TOK + i];
    s[threadIdx.x] = a;
    __syncthreads();
#pragma unroll
    for (int k = 512; k > 0; k >>= 1) {
        if (threadIdx.x < k) s[threadIdx.x] += s[threadIdx.x + k];
        __syncthreads();
    }
    if (threadIdx.x == 0) out[0] = (float)(s[0] / (double)N_TOK);
}

// ---------------------------------------------------------------------------
extern "C" void kernel_launch(void* const* d_in, const int* in_sizes, int n_in,
                              void* d_out, int out_size) {
    const float* w_in   = (const float*)d_in[0];
    const int*   target = (const int*)d_in[1];
    const float* head_w = (const float*)d_in[2];
    const float* head_b = (const float*)d_in[3];
    const float* t0w1   = (const float*)d_in[4];
    const float* t0w2   = (const float*)d_in[5];
    const float* t1w1   = (const float*)d_in[6];
    const float* t1w2   = (const float*)d_in[7];
    float* out = (float*)d_out;

    init_kernel<<<1, 32>>>();
    gather_kernel<<<(N_TOK + 255) / 256, 256>>>(target);
    convert_kernel<<<(WTOT + 255) / 256, 256>>>(w_in, head_w, t0w1, t0w2,
                                                t1w1, t1w2);

    // stage A: head (fused CE) + t0s1 + t1s1
    gemm256<<<dim3(32, 32, 3), 256>>>(head_b, 0);
    // stage B: t1s2 (fused CE) + t0s2 (fused CE)
    gemm256<<<dim3(625, 32, 2), 256>>>(head_b, 1);

    ce_merge<<<dim3(N_TOK, 3), 32>>>();
    reduce_kernel<<<1, 1024>>>(out);
}